// round 17
// baseline (speedup 1.0000x reference)
#include <cuda_runtime.h>
#include <math.h>

// Problem constants (B=64, C=1024, Q=128, D=128)
#define NB 64
#define NC 1024
#define NQ 128
#define ND 128
#define TC 64

// smem float offsets (monotone swizzled pitches: no row overlap possible)
#define OFF_A  0
#define SZ_A   8512
#define OFF_Q  (OFF_A + SZ_A)          // 8512
#define SZ_Q   17024
#define OFF_P  (OFF_Q + SZ_Q)          // 25536
#define SZ_P   16960
#define OFF_CT (OFF_P + SZ_P)          // 42496
#define OFF_QT (OFF_CT + 64)           // 42560
#define OFF_R1 (OFF_QT + 128)          // 42688
#define OFF_R2 (OFF_R1 + 256)          // 42944
#define SMEM_FLOATS (OFF_R2 + 256)     // 43200 -> 172800 bytes

__device__ float g_m[NB * NC];
__device__ float g_q2c[NB * ND];

__device__ __forceinline__ void ffma2(unsigned long long &acc,
                                      unsigned long long a,
                                      unsigned long long b) {
    asm("fma.rn.f32x2 %0, %1, %2, %0;" : "+l"(acc) : "l"(a), "l"(b));
}

__device__ __forceinline__ float2 up2(unsigned long long u) {
    float2 f;
    f.x = __int_as_float((int)(unsigned)(u & 0xffffffffULL));
    f.y = __int_as_float((int)(unsigned)(u >> 32));
    return f;
}

// Monotone swizzled row base (floats). Gap to next row = 132/136 >= 132 > 128:
// rows can NEVER overlap (the R5 bug was the &7 wraparound dropping the offset
// by 28 with only 4 floats of pad). Rows spaced 4 land 532 ≡ 20 banks apart:
// {20k mod 32} distinct for k=0..7 → conflict-free (unswizzled 528 ≡ 16 would
// alternate 2 positions → 4-way conflict).
__device__ __forceinline__ int rowAQ(int r) { return r * 132 + (r >> 2) * 4; }
__device__ __forceinline__ int rowP(int r)  { return r * 264 + (r >> 2) * 4; }

extern __shared__ float sm[];

__global__ void __launch_bounds__(512, 1)
k_main(const float* __restrict__ ctx, const float* __restrict__ qry,
       const float* __restrict__ W, const float* __restrict__ mask,
       float* __restrict__ out) {
    const int b = blockIdx.y;
    const int c0 = blockIdx.x * TC;
    const int tid = threadIdx.x;
    const int w = tid >> 5, l = tid & 31;
    const int tyl = l >> 3, txl = l & 7;
    const int cg = (w & 3) * 4 + tyl;     // 0..15, 4 c-rows each
    const int qg = (w >> 2) * 8 + txl;    // 0..31, 4 q-rows / 4 d each

    const float* ctxb = ctx + ((size_t)(b * NC + c0)) * ND;
    const float* qryb = qry + ((size_t)b) * NQ * ND;

    // ---- Stage Q (swizzled rows) + q_term + mask fold ----
    {
        const int q = tid >> 2, h = tid & 3;               // 4 threads per q-row
        const float* src = qryb + q * ND + h * 32;
        const int qb = OFF_Q + rowAQ(q) + h * 32;
        float qt = 0.f;
#pragma unroll
        for (int i = 0; i < 8; i++) {
            float4 v = ((const float4*)src)[i];
            int d = h * 32 + i * 4;
            qt += v.x * W[ND + d] + v.y * W[ND + d + 1] +
                  v.z * W[ND + d + 2] + v.w * W[ND + d + 3];
            *(float4*)&sm[qb + i * 4] = v;
        }
        qt += __shfl_xor_sync(0xffffffffu, qt, 1);
        qt += __shfl_xor_sync(0xffffffffu, qt, 2);
        if (h == 0)
            sm[OFF_QT + q] = qt + (1.0f - mask[b * NQ + q]) * (-1000000000.0f);
    }
    // ---- Stage Ac_s = context * w_s (swizzled) + c_term ----
    {
        const int c = tid >> 3, part = tid & 7;            // 8 threads per c-row
        const float* src = ctxb + c * ND + part * 16;
        const int ab = OFF_A + rowAQ(c) + part * 16;
        float ct = 0.f;
#pragma unroll
        for (int i = 0; i < 4; i++) {
            float4 v = ((const float4*)src)[i];
            int d = part * 16 + i * 4;
            ct += v.x * W[d] + v.y * W[d + 1] + v.z * W[d + 2] + v.w * W[d + 3];
            float4 s4;
            s4.x = v.x * W[2 * ND + d];
            s4.y = v.y * W[2 * ND + d + 1];
            s4.z = v.z * W[2 * ND + d + 2];
            s4.w = v.w * W[2 * ND + d + 3];
            *(float4*)&sm[ab + i * 4] = s4;
        }
        ct += __shfl_xor_sync(0xffffffffu, ct, 1);
        ct += __shfl_xor_sync(0xffffffffu, ct, 2);
        ct += __shfl_xor_sync(0xffffffffu, ct, 4);
        if (part == 0) sm[OFF_CT + c] = ct;
    }
    __syncthreads();

    // ---- S GEMM: 4c x 4q per thread, d-pair packed FFMA2 ----
    int abase[4], qbase[4];
#pragma unroll
    for (int i = 0; i < 4; i++) abase[i] = OFF_A + rowAQ(cg * 4 + i);
#pragma unroll
    for (int j = 0; j < 4; j++) qbase[j] = OFF_Q + rowAQ(qg * 4 + j);

    unsigned long long acc[4][4];
#pragma unroll
    for (int i = 0; i < 4; i++)
#pragma unroll
        for (int j = 0; j < 4; j++) acc[i][j] = 0ULL;

#pragma unroll 4
    for (int kk = 0; kk < ND; kk += 4) {
        ulonglong2 a[4], bq[4];
#pragma unroll
        for (int i = 0; i < 4; i++) a[i] = *(const ulonglong2*)&sm[abase[i] + kk];
#pragma unroll
        for (int j = 0; j < 4; j++) bq[j] = *(const ulonglong2*)&sm[qbase[j] + kk];
#pragma unroll
        for (int i = 0; i < 4; i++)
#pragma unroll
            for (int j = 0; j < 4; j++) {
                ffma2(acc[i][j], a[i].x, bq[j].x);
                ffma2(acc[i][j], a[i].y, bq[j].y);
            }
    }

    // ---- Softmax over q (two-stage: 8-lane shuffle + cross-warp smem) ----
    float ctv[4], qv[4];
#pragma unroll
    for (int i = 0; i < 4; i++) ctv[i] = sm[OFF_CT + cg * 4 + i];
#pragma unroll
    for (int j = 0; j < 4; j++) qv[j] = sm[OFF_QT + qg * 4 + j];

    float s[4][4];
#pragma unroll
    for (int i = 0; i < 4; i++) {
        float lm = -3.4e38f;
#pragma unroll
        for (int j = 0; j < 4; j++) {
            float2 f = up2(acc[i][j]);
            s[i][j] = f.x + f.y + ctv[i] + qv[j];
            lm = fmaxf(lm, s[i][j]);
        }
        lm = fmaxf(lm, __shfl_xor_sync(0xffffffffu, lm, 1));
        lm = fmaxf(lm, __shfl_xor_sync(0xffffffffu, lm, 2));
        lm = fmaxf(lm, __shfl_xor_sync(0xffffffffu, lm, 4));
        if (txl == 0) sm[OFF_R1 + (cg * 4 + i) * 4 + (w >> 2)] = lm;
    }
    __syncthreads();

    float M[4];
#pragma unroll
    for (int i = 0; i < 4; i++) {
        float4 m4 = *(const float4*)&sm[OFF_R1 + (cg * 4 + i) * 4];
        M[i] = fmaxf(fmaxf(m4.x, m4.y), fmaxf(m4.z, m4.w));
        float ls = 0.f;
#pragma unroll
        for (int j = 0; j < 4; j++) {
            float e = __expf(s[i][j] - M[i]);
            s[i][j] = e;
            ls += e;
        }
        ls += __shfl_xor_sync(0xffffffffu, ls, 1);
        ls += __shfl_xor_sync(0xffffffffu, ls, 2);
        ls += __shfl_xor_sync(0xffffffffu, ls, 4);
        if (txl == 0) sm[OFF_R2 + (cg * 4 + i) * 4 + (w >> 2)] = ls;
    }
    __syncthreads();

#pragma unroll
    for (int i = 0; i < 4; i++) {
        int c = cg * 4 + i;
        float4 s4 = *(const float4*)&sm[OFF_R2 + c * 4];
        float rr = __fdividef(1.0f, s4.x + s4.y + s4.z + s4.w);
        float p0 = s[i][0] * rr, p1 = s[i][1] * rr;
        float p2 = s[i][2] * rr, p3 = s[i][3] * rr;
        int pb = OFF_P + rowP(c) + 2 * (qg * 4);
        *(float4*)&sm[pb]     = make_float4(p0, p0, p1, p1);  // duplicated pairs
        *(float4*)&sm[pb + 4] = make_float4(p2, p2, p3, p3);
        if ((w >> 2) == 0 && txl == 0) g_m[b * NC + c0 + c] = M[i];
    }
    __syncthreads();

    // ---- c2q GEMM: 4c x 4d per thread, q-pair FFMA2 via duplicated P ----
    int pbase[4];
#pragma unroll
    for (int i = 0; i < 4; i++) pbase[i] = OFF_P + rowP(cg * 4 + i);
    const int dof = qg * 4;   // this thread's d-slice

    unsigned long long ca[4][2];
#pragma unroll
    for (int i = 0; i < 4; i++) { ca[i][0] = 0ULL; ca[i][1] = 0ULL; }

#pragma unroll 2
    for (int qq = 0; qq < NQ; qq += 4) {
        const int qsw = (qq >> 2) * 4;   // matches rowAQ for rows qq..qq+3
        ulonglong2 bq0 = *(const ulonglong2*)&sm[OFF_Q + (qq + 0) * 132 + qsw + dof];
        ulonglong2 bq1 = *(const ulonglong2*)&sm[OFF_Q + (qq + 1) * 132 + qsw + dof];
        ulonglong2 bq2 = *(const ulonglong2*)&sm[OFF_Q + (qq + 2) * 132 + qsw + dof];
        ulonglong2 bq3 = *(const ulonglong2*)&sm[OFF_Q + (qq + 3) * 132 + qsw + dof];
#pragma unroll
        for (int i = 0; i < 4; i++) {
            ulonglong2 pA = *(const ulonglong2*)&sm[pbase[i] + 2 * qq];
            ulonglong2 pB = *(const ulonglong2*)&sm[pbase[i] + 2 * qq + 4];
            ffma2(ca[i][0], pA.x, bq0.x); ffma2(ca[i][1], pA.x, bq0.y);
            ffma2(ca[i][0], pA.y, bq1.x); ffma2(ca[i][1], pA.y, bq1.y);
            ffma2(ca[i][0], pB.x, bq2.x); ffma2(ca[i][1], pB.x, bq2.y);
            ffma2(ca[i][0], pB.y, bq3.x); ffma2(ca[i][1], pB.y, bq3.y);
        }
    }

    // ---- Epilogue: chunks 0..2 ----
#pragma unroll
    for (int i = 0; i < 4; i++) {
        int c = c0 + cg * 4 + i;
        const float4 x = *(const float4*)&ctx[((size_t)(b * NC + c)) * ND + dof];
        float2 y0 = up2(ca[i][0]), y1 = up2(ca[i][1]);
        float4 cq = make_float4(y0.x, y0.y, y1.x, y1.y);
        float* ob = out + ((size_t)(b * NC + c)) * (4 * ND);
        *(float4*)&ob[dof] = x;
        *(float4*)&ob[ND + dof] = cq;
        *(float4*)&ob[2 * ND + dof] =
            make_float4(x.x * cq.x, x.y * cq.y, x.z * cq.z, x.w * cq.w);
    }
}

__global__ void __launch_bounds__(256, 4)
k_q2c(const float* __restrict__ ctx) {
    __shared__ float sp[NC];
    __shared__ float sr[8];
    __shared__ float sr2[8];
    __shared__ float spart[256];
    const int b = blockIdx.x;
    const int tid = threadIdx.x;

    float v[4];
    float mx = -3.4e38f;
#pragma unroll
    for (int k = 0; k < 4; k++) {
        v[k] = g_m[b * NC + tid + 256 * k];
        mx = fmaxf(mx, v[k]);
    }
#pragma unroll
    for (int o = 16; o > 0; o >>= 1)
        mx = fmaxf(mx, __shfl_xor_sync(0xffffffffu, mx, o));
    if ((tid & 31) == 0) sr[tid >> 5] = mx;
    __syncthreads();
    float M = sr[0];
#pragma unroll
    for (int w = 1; w < 8; w++) M = fmaxf(M, sr[w]);

    float s = 0.f;
#pragma unroll
    for (int k = 0; k < 4; k++) {
        float e = __expf(v[k] - M);
        sp[tid + 256 * k] = e;
        s += e;
    }
#pragma unroll
    for (int o = 16; o > 0; o >>= 1)
        s += __shfl_xor_sync(0xffffffffu, s, o);
    if ((tid & 31) == 0) sr2[tid >> 5] = s;
    __syncthreads();
    float T = 0.f;
#pragma unroll
    for (int w = 0; w < 8; w++) T += sr2[w];
    float rs = __fdividef(1.0f, T);

    const int d = tid & 127, half = tid >> 7;
    const float* cb = ctx + ((size_t)b) * NC * ND + ((size_t)half) * 512 * ND + d;
    float a0 = 0.f, a1 = 0.f, a2 = 0.f, a3 = 0.f;
    const int cbase = half * 512;
#pragma unroll 4
    for (int c = 0; c < 512; c += 4) {
        a0 += sp[cbase + c + 0] * cb[(size_t)(c + 0) * ND];
        a1 += sp[cbase + c + 1] * cb[(size_t)(c + 1) * ND];
        a2 += sp[cbase + c + 2] * cb[(size_t)(c + 2) * ND];
        a3 += sp[cbase + c + 3] * cb[(size_t)(c + 3) * ND];
    }
    spart[tid] = (a0 + a1) + (a2 + a3);
    __syncthreads();
    if (tid < 128)
        g_q2c[b * ND + tid] = (spart[tid] + spart[tid + 128]) * rs;
}

__global__ void __launch_bounds__(256, 4)
k_out4(const float* __restrict__ ctx, float* __restrict__ out) {
    __shared__ float q2[ND];
    const int b = blockIdx.y;
    const int r0 = blockIdx.x * 16;
    if (threadIdx.x < ND) q2[threadIdx.x] = g_q2c[b * ND + threadIdx.x];
    __syncthreads();
    for (int vid = threadIdx.x; vid < 16 * 32; vid += 256) {
        int r = vid >> 5;
        int d4 = (vid & 31) * 4;
        int c = r0 + r;
        float4 x = *(const float4*)&ctx[((size_t)(b * NC + c)) * ND + d4];
        float4 qv = *(const float4*)&q2[d4];
        float4 o = make_float4(x.x * qv.x, x.y * qv.y, x.z * qv.z, x.w * qv.w);
        *(float4*)&out[((size_t)(b * NC + c)) * (4 * ND) + 3 * ND + d4] = o;
    }
}

extern "C" void kernel_launch(void* const* d_in, const int* in_sizes, int n_in,
                              void* d_out, int out_size) {
    const float* ctx  = (const float*)d_in[0];
    const float* qry  = (const float*)d_in[1];
    const float* W    = (const float*)d_in[2];
    const float* mask = (const float*)d_in[3];
    float* out = (float*)d_out;

    cudaFuncSetAttribute(k_main, cudaFuncAttributeMaxDynamicSharedMemorySize,
                         SMEM_FLOATS * (int)sizeof(float));

    k_main<<<dim3(NC / TC, NB), 512, SMEM_FLOATS * sizeof(float)>>>(ctx, qry, W, mask, out);
    k_q2c<<<NB, 256>>>(ctx);
    k_out4<<<dim3(NC / 16, NB), 256>>>(ctx, out);
}